// round 9
// baseline (speedup 1.0000x reference)
#include <cuda_runtime.h>
#include <math_constants.h>
#include <cstdint>

#define B 4
#define NH 32
#define HD 128
#define HID 4096
#define S_PAST 8192
#define KV (S_PAST + 1)
#define HEAVY 2048
#define OUTL 16
#define BH (B * NH)

#define RSQRT_HD 0.08838834764831845f   // 1/sqrt(128)
#define RSQRT_OUTL 0.25f                // 1/sqrt(16)
#define FULLMASK 0xffffffffu

// ---------------- scratch (device globals; no allocation) ----------------
__device__ float g_qkv[3 * B * HID];     // pre-rope q,k,v
__device__ float g_q[BH * HD];           // roped q
__device__ float g_knew[BH * HD];        // roped k (appended position)
__device__ float g_vnew[BH * HD];        // v (appended position)
__device__ float g_gq[BH * OUTL];        // quantized gathered q
__device__ float g_attn[BH * KV];        // full attention logits
__device__ float g_gattn[BH * KV];       // label (quantized) logits
__device__ unsigned int g_mu[BH];        // flipped-uint running max of attn
__device__ float g_kth[BH];
__device__ float g_z[BH];                // softmax denominator (unnormalized)
__device__ float g_hout[B * HID];        // per-head outputs (un-normalized)

__device__ __forceinline__ unsigned int fflip(float f) {
    unsigned int u = __float_as_uint(f);
    return (u & 0x80000000u) ? ~u : (u | 0x80000000u);
}
__device__ __forceinline__ float funflip(unsigned int u) {
    return __uint_as_float((u & 0x80000000u) ? (u & 0x7FFFFFFFu) : ~u);
}

// ---------------- K1: fused QKV GEMV ----------------
__global__ void qkv_gemv_kernel(const float* __restrict__ hid,
                                const float* __restrict__ Wq,
                                const float* __restrict__ Wk,
                                const float* __restrict__ Wv) {
    int t = blockIdx.x;
    int which = t >> 12;           // HID = 4096 = 2^12
    int row = t & (HID - 1);
    const float* W = (which == 0) ? Wq : (which == 1) ? Wk : Wv;
    const float4* w4 = reinterpret_cast<const float4*>(W + (size_t)row * HID);
    const float4* h4 = reinterpret_cast<const float4*>(hid);

    float a0 = 0.f, a1 = 0.f, a2 = 0.f, a3 = 0.f;
#pragma unroll 4
    for (int i = threadIdx.x; i < HID / 4; i += 128) {
        float4 w = __ldg(&w4[i]);
        float4 h;
        h = h4[i];
        a0 += w.x * h.x + w.y * h.y + w.z * h.z + w.w * h.w;
        h = h4[i + (HID / 4)];
        a1 += w.x * h.x + w.y * h.y + w.z * h.z + w.w * h.w;
        h = h4[i + 2 * (HID / 4)];
        a2 += w.x * h.x + w.y * h.y + w.z * h.z + w.w * h.w;
        h = h4[i + 3 * (HID / 4)];
        a3 += w.x * h.x + w.y * h.y + w.z * h.z + w.w * h.w;
    }
#pragma unroll
    for (int o = 16; o; o >>= 1) {
        a0 += __shfl_down_sync(FULLMASK, a0, o);
        a1 += __shfl_down_sync(FULLMASK, a1, o);
        a2 += __shfl_down_sync(FULLMASK, a2, o);
        a3 += __shfl_down_sync(FULLMASK, a3, o);
    }
    __shared__ float s[4][4];
    int warp = threadIdx.x >> 5, lane = threadIdx.x & 31;
    if (lane == 0) { s[warp][0] = a0; s[warp][1] = a1; s[warp][2] = a2; s[warp][3] = a3; }
    __syncthreads();
    if (threadIdx.x < 4) {
        float sum = s[0][threadIdx.x] + s[1][threadIdx.x] + s[2][threadIdx.x] + s[3][threadIdx.x];
        g_qkv[((size_t)which * B + threadIdx.x) * HID + row] = sum;
    }
}

// ---------------- K2: RoPE + gq quantization + init accumulators ----------------
__global__ void rope_kernel(const float* __restrict__ cosp,
                            const float* __restrict__ sinp,
                            const int* __restrict__ schan) {
    int bh = blockIdx.x;
    int b = bh >> 5, h = bh & 31;
    int d = threadIdx.x;

    g_hout[bh * HD + d] = 0.f;     // zero accumulator for K5 atomics
    if (d == 0) { g_mu[bh] = 0u; g_z[bh] = 0.f; }

    float q = g_qkv[(0 * B + b) * HID + h * HD + d];
    float k = g_qkv[(1 * B + b) * HID + h * HD + d];
    float v = g_qkv[(2 * B + b) * HID + h * HD + d];
    float c = cosp[b * HD + d];
    float sn = sinp[b * HD + d];

    __shared__ float sq[HD], sk[HD], sqr[HD];
    sq[d] = q; sk[d] = k;
    __syncthreads();
    float rq = (d < HD / 2) ? -sq[d + HD / 2] : sq[d - HD / 2];
    float rk = (d < HD / 2) ? -sk[d + HD / 2] : sk[d - HD / 2];
    float qr = q * c + rq * sn;
    float kr = k * c + rk * sn;
    g_q[bh * HD + d] = qr;
    g_knew[bh * HD + d] = kr;
    g_vnew[bh * HD + d] = v;
    sqr[d] = qr;
    __syncthreads();

    if (d < 32) {
        float val = 0.f;
        if (d < OUTL) val = sqr[schan[h * HD + d]];
        float mn = (d < OUTL) ? val : CUDART_INF_F;
        float mx = (d < OUTL) ? val : -CUDART_INF_F;
#pragma unroll
        for (int o = 16; o; o >>= 1) {
            mn = fminf(mn, __shfl_xor_sync(FULLMASK, mn, o));
            mx = fmaxf(mx, __shfl_xor_sync(FULLMASK, mx, o));
        }
        float range = mx - mn;
        if (range == 0.f) range = 1.f;
        float scale = 15.f / range;
        float qq = fminf(fmaxf(rintf((val - mn) * scale), 0.f), 15.f);
        float deq = qq / scale + mn;
        if (d < OUTL) g_gq[bh * OUTL + d] = deq;
    }
}

// ---------------- K3: attn + gattn over full K (R3 layout, 4 rows/warp) -----
__global__ void attn_kernel(const float* __restrict__ pk,
                            const int* __restrict__ schan) {
    __shared__ float sq[HD];
    __shared__ float sgq[OUTL];
    __shared__ int sch[OUTL];
    __shared__ float swmax[8];
    int bh = blockIdx.y;
    int h = bh & 31;
    int tid = threadIdx.x;
    if (tid < HD) sq[tid] = g_q[bh * HD + tid];
    if (tid < OUTL) { sgq[tid] = g_gq[bh * OUTL + tid]; sch[tid] = schan[h * HD + tid]; }
    __syncthreads();

    int warp = tid >> 5, lane = tid & 31;
    float4 q4 = reinterpret_cast<const float4*>(sq)[lane];
    float gqv = (lane < OUTL) ? sgq[lane] : 0.f;
    int chv = (lane < OUTL) ? sch[lane] : 0;

    int j0 = blockIdx.x * 32 + warp;   // rows j0, j0+8, j0+16, j0+24

    // ---- batched row loads: maximize MLP ----
    const float* krow[4];
    float4 k4[4];
#pragma unroll
    for (int r = 0; r < 4; r++) {
        int j = j0 + r * 8;
        int jc = (j < KV) ? j : KV - 1;
        krow[r] = (jc < S_PAST) ? pk + ((size_t)bh * S_PAST + jc) * HD
                                : g_knew + (size_t)bh * HD;
    }
#pragma unroll
    for (int r = 0; r < 4; r++)
        k4[r] = __ldg(&reinterpret_cast<const float4*>(krow[r])[lane]);

    float gk[4];
#pragma unroll
    for (int r = 0; r < 4; r++)
        gk[r] = (lane < OUTL) ? __ldg(&krow[r][chv]) : 0.f;

    // ---- interleaved reductions (4-way ILP) ----
    float dot[4], mn[4], mx[4];
#pragma unroll
    for (int r = 0; r < 4; r++) {
        dot[r] = fmaf(k4[r].x, q4.x, fmaf(k4[r].y, q4.y,
                 fmaf(k4[r].z, q4.z, k4[r].w * q4.w)));
        mn[r] = (lane < OUTL) ? gk[r] : CUDART_INF_F;
        mx[r] = (lane < OUTL) ? gk[r] : -CUDART_INF_F;
    }
    // dot: full-warp 5 rounds (butterfly -> broadcast to all lanes)
#pragma unroll
    for (int o = 16; o; o >>= 1)
#pragma unroll
        for (int r = 0; r < 4; r++)
            dot[r] += __shfl_xor_sync(FULLMASK, dot[r], o);
    // mn/mx: 4 rounds suffice (correct within each 16-lane group; only
    // lanes 0..15 consume them)
#pragma unroll
    for (int o = 8; o; o >>= 1)
#pragma unroll
        for (int r = 0; r < 4; r++) {
            mn[r] = fminf(mn[r], __shfl_xor_sync(FULLMASK, mn[r], o));
            mx[r] = fmaxf(mx[r], __shfl_xor_sync(FULLMASK, mx[r], o));
        }
    float p[4], a[4];
#pragma unroll
    for (int r = 0; r < 4; r++) {
        float range = mx[r] - mn[r];
        if (range == 0.f) range = 1.f;
        float scale = 15.f / range;
        float gkq = fminf(fmaxf(rintf((gk[r] - mn[r]) * scale), 0.f), 15.f) / scale + mn[r];
        p[r] = (lane < OUTL) ? gqv * gkq : 0.f;
        a[r] = dot[r] * RSQRT_HD;
    }
#pragma unroll
    for (int o = 8; o; o >>= 1)
#pragma unroll
        for (int r = 0; r < 4; r++)
            p[r] += __shfl_xor_sync(FULLMASK, p[r], o);   // lane 0 correct

    // block max of a (a[] is uniform across lanes -> no extra shuffle)
    float am = -CUDART_INF_F;
#pragma unroll
    for (int r = 0; r < 4; r++)
        if (j0 + r * 8 < KV) am = fmaxf(am, a[r]);

    if (lane == 0) {
#pragma unroll
        for (int r = 0; r < 4; r++) {
            int j = j0 + r * 8;
            if (j < KV) {
                g_attn[(size_t)bh * KV + j] = a[r];
                g_gattn[(size_t)bh * KV + j] = p[r] * RSQRT_OUTL;
            }
        }
        swmax[warp] = am;
    }
    __syncthreads();
    if (tid == 0) {
        float bm = swmax[0];
#pragma unroll
        for (int w = 1; w < 8; w++) bm = fmaxf(bm, swmax[w]);
        if (bm > -CUDART_INF_F) atomicMax(&g_mu[bh], fflip(bm));
    }
}

// ---------------- K4: radix-select kth largest gattn (radix only) ----------
#define ST 512                 // threads
#define NC 8                   // privatized hist copies (2 warps/copy)
__global__ void select_kernel() {
    __shared__ unsigned int skey[KV];        // 32772 B
    __shared__ unsigned int hist[NC][256];   // 8192 B
    __shared__ unsigned int s_prefix, s_k;

    int bh = blockIdx.x;
    int tid = threadIdx.x;
    int warp = tid >> 5, lane = tid & 31;
    int copy = warp >> 1;

    for (int j = tid; j < KV; j += ST) {
        skey[j] = fflip(g_gattn[(size_t)bh * KV + j]);
    }
    if (tid == 0) { s_prefix = 0u; s_k = HEAVY; }
    __syncthreads();

#pragma unroll
    for (int pass = 0; pass < 4; pass++) {
        int shift = 24 - 8 * pass;
        for (int i = tid; i < NC * 256; i += ST) ((unsigned int*)hist)[i] = 0u;
        __syncthreads();
        unsigned int pfx = s_prefix;
        unsigned int k0 = s_k;
        unsigned int pmask = (pass == 0) ? 0u : (0xFFFFFFFFu << (shift + 8));

        for (int base = 0; base < KV; base += ST) {
            int j = base + tid;
            bool inb = (j < KV);
            unsigned int u = inb ? skey[j] : 0u;
            bool active = inb && ((u & pmask) == pfx);
            unsigned int bin = (u >> shift) & 255u;
            unsigned int act = __ballot_sync(FULLMASK, active);
            if (active) {
                unsigned int peers = __match_any_sync(act, bin);
                int leader = __ffs(peers) - 1;
                if (lane == leader)
                    atomicAdd(&hist[copy][bin], __popc(peers));
            }
        }
        __syncthreads();

        // warp 0 alone: reduce copies + suffix-select
        if (warp == 0) {
            unsigned int cnt[8];
            unsigned int tot = 0u;
#pragma unroll
            for (int i = 0; i < 8; i++) {
                unsigned int c = 0u;
#pragma unroll
                for (int cc = 0; cc < NC; cc++) c += hist[cc][lane * 8 + i];
                cnt[i] = c;
                tot += c;
            }
            unsigned int s = tot;
#pragma unroll
            for (int o = 1; o < 32; o <<= 1) {
                unsigned int v = __shfl_down_sync(FULLMASK, s, o);
                if (lane + o < 32) s += v;
            }
            unsigned int higher = s - tot;
            if (higher < k0 && higher + tot >= k0) {
                unsigned int run = higher;
#pragma unroll
                for (int i = 7; i >= 0; i--) {
                    run += cnt[i];
                    if (run >= k0) {
                        s_prefix = pfx | ((unsigned int)(lane * 8 + i) << shift);
                        s_k = k0 - (run - cnt[i]);
                        break;
                    }
                }
            }
        }
        __syncthreads();
    }

    if (tid == 0) g_kth[bh] = funflip(s_prefix);
}

// ---------------- K5: selective weighted V accumulation + z sum (split 32x) ----
__global__ void outv_kernel(const float* __restrict__ pv) {
    int bh = blockIdx.y;
    int tid = threadIdx.x;
    int warp = tid >> 5, lane = tid & 31;
    float kth = g_kth[bh], m = funflip(g_mu[bh]);

    float4 acc = make_float4(0.f, 0.f, 0.f, 0.f);
    float z = 0.f;
    for (int j = blockIdx.x * 8 + warp; j < KV; j += 256) {
        float g = g_gattn[(size_t)bh * KV + j];
        if (g >= kth) {
            float w = __expf(g_attn[(size_t)bh * KV + j] - m);
            z += w;
            const float* vrow = (j < S_PAST)
                ? pv + ((size_t)bh * S_PAST + j) * HD
                : g_vnew + (size_t)bh * HD;
            float4 v4 = __ldg(&reinterpret_cast<const float4*>(vrow)[lane]);
            acc.x += w * v4.x; acc.y += w * v4.y; acc.z += w * v4.z; acc.w += w * v4.w;
        }
    }
    __shared__ float sacc[8][HD];
    __shared__ float sz[8];
    reinterpret_cast<float4*>(&sacc[warp][0])[lane] = acc;
    if (lane == 0) sz[warp] = z;
    __syncthreads();
    if (tid < HD) {
        float s = 0.f;
#pragma unroll
        for (int w = 0; w < 8; w++) s += sacc[w][tid];
        atomicAdd(&g_hout[bh * HD + tid], s);
    }
    if (tid == 0) {
        float t = 0.f;
#pragma unroll
        for (int w = 0; w < 8; w++) t += sz[w];
        atomicAdd(&g_z[bh], t);
    }
}

// ---------------- K6: output GEMV (normalize-by-z folded in) ----------------
__global__ void out_gemv_kernel(const float* __restrict__ Wo,
                                float* __restrict__ out) {
    __shared__ float sinv[BH];
    int tid = threadIdx.x;
    if (tid < BH) sinv[tid] = 1.f / g_z[tid];
    __syncthreads();

    int row = blockIdx.x;
    const float4* w4 = reinterpret_cast<const float4*>(Wo + (size_t)row * HID);
    const float4* h4 = reinterpret_cast<const float4*>(g_hout);

    float a0 = 0.f, a1 = 0.f, a2 = 0.f, a3 = 0.f;
#pragma unroll 4
    for (int i = tid; i < HID / 4; i += 128) {
        int hh = i >> 5;                 // head index 0..31
        float4 w = __ldg(&w4[i]);
        float4 h;
        float s;
        h = h4[i];                 s = sinv[hh];
        a0 += s * (w.x * h.x + w.y * h.y + w.z * h.z + w.w * h.w);
        h = h4[i + (HID / 4)];     s = sinv[32 + hh];
        a1 += s * (w.x * h.x + w.y * h.y + w.z * h.z + w.w * h.w);
        h = h4[i + 2 * (HID / 4)]; s = sinv[64 + hh];
        a2 += s * (w.x * h.x + w.y * h.y + w.z * h.z + w.w * h.w);
        h = h4[i + 3 * (HID / 4)]; s = sinv[96 + hh];
        a3 += s * (w.x * h.x + w.y * h.y + w.z * h.z + w.w * h.w);
    }
#pragma unroll
    for (int o = 16; o; o >>= 1) {
        a0 += __shfl_down_sync(FULLMASK, a0, o);
        a1 += __shfl_down_sync(FULLMASK, a1, o);
        a2 += __shfl_down_sync(FULLMASK, a2, o);
        a3 += __shfl_down_sync(FULLMASK, a3, o);
    }
    __shared__ float s[4][4];
    int warp = tid >> 5, lane = tid & 31;
    if (lane == 0) { s[warp][0] = a0; s[warp][1] = a1; s[warp][2] = a2; s[warp][3] = a3; }
    __syncthreads();
    if (tid < 4) {
        float sum = s[0][tid] + s[1][tid] + s[2][tid] + s[3][tid];
        out[(size_t)tid * HID + row] = sum;
    }
}

// ---------------- launch ----------------
extern "C" void kernel_launch(void* const* d_in, const int* in_sizes, int n_in,
                              void* d_out, int out_size) {
    const float* hid  = (const float*)d_in[0];
    const float* pk   = (const float*)d_in[1];
    const float* pv   = (const float*)d_in[2];
    const float* cosp = (const float*)d_in[3];
    const float* sinp = (const float*)d_in[4];
    const int*   sch  = (const int*)d_in[5];
    const float* Wq   = (const float*)d_in[6];
    const float* Wk   = (const float*)d_in[7];
    const float* Wv   = (const float*)d_in[8];
    const float* Wo   = (const float*)d_in[9];
    float* out = (float*)d_out;

    qkv_gemv_kernel<<<3 * HID, 128>>>(hid, Wq, Wk, Wv);
    rope_kernel<<<BH, 128>>>(cosp, sinp, sch);
    attn_kernel<<<dim3((KV + 31) / 32, BH), 256>>>(pk, sch);
    select_kernel<<<BH, ST>>>();
    outv_kernel<<<dim3(32, BH), 256>>>(pv);
    out_gemv_kernel<<<HID, 128>>>(Wo, out);
}

// round 10
// speedup vs baseline: 1.6192x; 1.6192x over previous
#include <cuda_runtime.h>
#include <math_constants.h>
#include <cstdint>

#define B 4
#define NH 32
#define HD 128
#define HID 4096
#define S_PAST 8192
#define KV (S_PAST + 1)
#define HEAVY 2048
#define OUTL 16
#define BH (B * NH)

#define RSQRT_HD 0.08838834764831845f   // 1/sqrt(128)
#define RSQRT_OUTL 0.25f                // 1/sqrt(16)
#define FULLMASK 0xffffffffu

// ---------------- scratch (device globals; no allocation) ----------------
__device__ float g_qkv[3 * B * HID];     // pre-rope q,k,v
__device__ float g_q[BH * HD];           // roped q
__device__ float g_knew[BH * HD];        // roped k (appended position)
__device__ float g_vnew[BH * HD];        // v (appended position)
__device__ float g_gq[BH * OUTL];        // quantized gathered q
__device__ float g_attn[BH * KV];        // full attention logits
__device__ float g_gattn[BH * KV];       // label (quantized) logits
__device__ float g_kth[BH];
__device__ float g_m[BH];
__device__ float g_invZ[BH];
__device__ float g_hout[B * HID];        // per-head outputs, (b, h*HD+d)

// ---------------- K1: fused QKV GEMV ----------------
__global__ void qkv_gemv_kernel(const float* __restrict__ hid,
                                const float* __restrict__ Wq,
                                const float* __restrict__ Wk,
                                const float* __restrict__ Wv) {
    int t = blockIdx.x;
    int which = t >> 12;           // HID = 4096 = 2^12
    int row = t & (HID - 1);
    const float* W = (which == 0) ? Wq : (which == 1) ? Wk : Wv;
    const float4* w4 = reinterpret_cast<const float4*>(W + (size_t)row * HID);
    const float4* h4 = reinterpret_cast<const float4*>(hid);

    float a0 = 0.f, a1 = 0.f, a2 = 0.f, a3 = 0.f;
    for (int i = threadIdx.x; i < HID / 4; i += blockDim.x) {
        float4 w = w4[i];
        float4 h;
        h = h4[i];
        a0 += w.x * h.x + w.y * h.y + w.z * h.z + w.w * h.w;
        h = h4[i + (HID / 4)];
        a1 += w.x * h.x + w.y * h.y + w.z * h.z + w.w * h.w;
        h = h4[i + 2 * (HID / 4)];
        a2 += w.x * h.x + w.y * h.y + w.z * h.z + w.w * h.w;
        h = h4[i + 3 * (HID / 4)];
        a3 += w.x * h.x + w.y * h.y + w.z * h.z + w.w * h.w;
    }
#pragma unroll
    for (int o = 16; o; o >>= 1) {
        a0 += __shfl_down_sync(FULLMASK, a0, o);
        a1 += __shfl_down_sync(FULLMASK, a1, o);
        a2 += __shfl_down_sync(FULLMASK, a2, o);
        a3 += __shfl_down_sync(FULLMASK, a3, o);
    }
    __shared__ float s[4][4];
    int warp = threadIdx.x >> 5, lane = threadIdx.x & 31;
    if (lane == 0) { s[warp][0] = a0; s[warp][1] = a1; s[warp][2] = a2; s[warp][3] = a3; }
    __syncthreads();
    if (threadIdx.x < 4) {
        float sum = s[0][threadIdx.x] + s[1][threadIdx.x] + s[2][threadIdx.x] + s[3][threadIdx.x];
        g_qkv[((size_t)which * B + threadIdx.x) * HID + row] = sum;
    }
}

// ---------------- K2: RoPE + gq quantization + zero g_hout ----------------
__global__ void rope_kernel(const float* __restrict__ cosp,
                            const float* __restrict__ sinp,
                            const int* __restrict__ schan) {
    int bh = blockIdx.x;
    int b = bh >> 5, h = bh & 31;
    int d = threadIdx.x;

    g_hout[bh * HD + d] = 0.f;   // zero accumulator for K5 atomics

    float q = g_qkv[(0 * B + b) * HID + h * HD + d];
    float k = g_qkv[(1 * B + b) * HID + h * HD + d];
    float v = g_qkv[(2 * B + b) * HID + h * HD + d];
    float c = cosp[b * HD + d];
    float sn = sinp[b * HD + d];

    __shared__ float sq[HD], sk[HD], sqr[HD];
    sq[d] = q; sk[d] = k;
    __syncthreads();
    float rq = (d < HD / 2) ? -sq[d + HD / 2] : sq[d - HD / 2];
    float rk = (d < HD / 2) ? -sk[d + HD / 2] : sk[d - HD / 2];
    float qr = q * c + rq * sn;
    float kr = k * c + rk * sn;
    g_q[bh * HD + d] = qr;
    g_knew[bh * HD + d] = kr;
    g_vnew[bh * HD + d] = v;
    sqr[d] = qr;
    __syncthreads();

    if (d < 32) {
        float val = 0.f;
        if (d < OUTL) val = sqr[schan[h * HD + d]];
        float mn = (d < OUTL) ? val : CUDART_INF_F;
        float mx = (d < OUTL) ? val : -CUDART_INF_F;
#pragma unroll
        for (int o = 16; o; o >>= 1) {
            mn = fminf(mn, __shfl_xor_sync(FULLMASK, mn, o));
            mx = fmaxf(mx, __shfl_xor_sync(FULLMASK, mx, o));
        }
        float range = mx - mn;
        if (range == 0.f) range = 1.f;
        float scale = 15.f / range;
        float qq = fminf(fmaxf(rintf((val - mn) * scale), 0.f), 15.f);
        float deq = qq / scale + mn;
        if (d < OUTL) g_gq[bh * OUTL + d] = deq;
    }
}

// ---------------- K3: attn + gattn over full K (4 rows/warp, batched loads) ----
__global__ void attn_kernel(const float* __restrict__ pk,
                            const int* __restrict__ schan) {
    __shared__ float sq[HD];
    __shared__ float sgq[OUTL];
    __shared__ int sch[OUTL];
    int bh = blockIdx.y;
    int h = bh & 31;
    int tid = threadIdx.x;
    if (tid < HD) sq[tid] = g_q[bh * HD + tid];
    else if (tid < HD + OUTL) sgq[tid - HD] = g_gq[bh * OUTL + (tid - HD)];
    else if (tid < HD + 2 * OUTL) sch[tid - HD - OUTL] = schan[h * HD + (tid - HD - OUTL)];
    __syncthreads();

    int warp = tid >> 5, lane = tid & 31;
    float4 q4 = reinterpret_cast<const float4*>(sq)[lane];
    float gqv = (lane < OUTL) ? sgq[lane] : 0.f;
    int chv = (lane < OUTL) ? sch[lane] : 0;

    int j0 = blockIdx.x * 32 + warp;   // rows j0, j0+8, j0+16, j0+24

    // ---- batched row loads: maximize MLP ----
    const float* krow[4];
    float4 k4[4];
#pragma unroll
    for (int r = 0; r < 4; r++) {
        int j = j0 + r * 8;
        int jc = (j < KV) ? j : KV - 1;
        krow[r] = (jc < S_PAST) ? pk + ((size_t)bh * S_PAST + jc) * HD
                                : g_knew + (size_t)bh * HD;
    }
#pragma unroll
    for (int r = 0; r < 4; r++)
        k4[r] = __ldg(&reinterpret_cast<const float4*>(krow[r])[lane]);

    float gk[4];
#pragma unroll
    for (int r = 0; r < 4; r++)
        gk[r] = (lane < OUTL) ? __ldg(&krow[r][chv]) : 0.f;

    // ---- interleaved reductions (4-way ILP over SHFL latency) ----
    float dot[4], mn[4], mx[4];
#pragma unroll
    for (int r = 0; r < 4; r++) {
        dot[r] = fmaf(k4[r].x, q4.x, fmaf(k4[r].y, q4.y,
                 fmaf(k4[r].z, q4.z, k4[r].w * q4.w)));
        mn[r] = (lane < OUTL) ? gk[r] : CUDART_INF_F;
        mx[r] = (lane < OUTL) ? gk[r] : -CUDART_INF_F;
    }
#pragma unroll
    for (int o = 16; o; o >>= 1) {
#pragma unroll
        for (int r = 0; r < 4; r++) {
            dot[r] += __shfl_xor_sync(FULLMASK, dot[r], o);
            mn[r] = fminf(mn[r], __shfl_xor_sync(FULLMASK, mn[r], o));
            mx[r] = fmaxf(mx[r], __shfl_xor_sync(FULLMASK, mx[r], o));
        }
    }
    float p[4];
#pragma unroll
    for (int r = 0; r < 4; r++) {
        float range = mx[r] - mn[r];
        if (range == 0.f) range = 1.f;
        float scale = 15.f / range;
        float gkq = fminf(fmaxf(rintf((gk[r] - mn[r]) * scale), 0.f), 15.f) / scale + mn[r];
        p[r] = (lane < OUTL) ? gqv * gkq : 0.f;
    }
#pragma unroll
    for (int o = 8; o; o >>= 1)
#pragma unroll
        for (int r = 0; r < 4; r++)
            p[r] += __shfl_xor_sync(FULLMASK, p[r], o);   // lanes 0..15 suffice

    if (lane == 0) {
#pragma unroll
        for (int r = 0; r < 4; r++) {
            int j = j0 + r * 8;
            if (j < KV) {
                g_attn[(size_t)bh * KV + j] = dot[r] * RSQRT_HD;
                g_gattn[(size_t)bh * KV + j] = p[r] * RSQRT_OUTL;
            }
        }
    }
}

// ---------------- K4: radix-select + softmax stats (warp0 bin select) ----
#define ST 512                 // threads
#define NC 8                   // privatized hist copies (2 warps/copy)
__global__ void select_kernel() {
    __shared__ unsigned int skey[KV];        // 32772 B
    __shared__ unsigned int hist[NC][256];   // 8192 B
    __shared__ float sred[ST / 32 + 1];
    __shared__ unsigned int s_prefix, s_k;

    int bh = blockIdx.x;
    int tid = threadIdx.x;
    int warp = tid >> 5, lane = tid & 31;
    int copy = warp >> 1;

    for (int j = tid; j < KV; j += ST) {
        unsigned int u = __float_as_uint(g_gattn[(size_t)bh * KV + j]);
        u = (u & 0x80000000u) ? ~u : (u | 0x80000000u);  // monotonic map
        skey[j] = u;
    }
    if (tid == 0) { s_prefix = 0u; s_k = HEAVY; }
    __syncthreads();

#pragma unroll
    for (int pass = 0; pass < 4; pass++) {
        int shift = 24 - 8 * pass;
        for (int i = tid; i < NC * 256; i += ST) ((unsigned int*)hist)[i] = 0u;
        __syncthreads();
        unsigned int pfx = s_prefix;
        unsigned int k0 = s_k;
        unsigned int pmask = (pass == 0) ? 0u : (0xFFFFFFFFu << (shift + 8));

        for (int base = 0; base < KV; base += ST) {
            int j = base + tid;
            bool inb = (j < KV);
            unsigned int u = inb ? skey[j] : 0u;
            bool active = inb && ((u & pmask) == pfx);
            unsigned int bin = (u >> shift) & 255u;
            unsigned int act = __ballot_sync(FULLMASK, active);
            if (active) {
                unsigned int peers = __match_any_sync(act, bin);
                int leader = __ffs(peers) - 1;
                if (lane == leader)
                    atomicAdd(&hist[copy][bin], __popc(peers));
            }
        }
        __syncthreads();

        // warp 0 alone: reduce copies + suffix-select (no block barriers inside)
        if (warp == 0) {
            unsigned int cnt[8];
            unsigned int tot = 0u;
#pragma unroll
            for (int i = 0; i < 8; i++) {
                unsigned int c = 0u;
#pragma unroll
                for (int cc = 0; cc < NC; cc++) c += hist[cc][lane * 8 + i];
                cnt[i] = c;
                tot += c;
            }
            // inclusive suffix scan over lanes
            unsigned int s = tot;
#pragma unroll
            for (int o = 1; o < 32; o <<= 1) {
                unsigned int v = __shfl_down_sync(FULLMASK, s, o);
                if (lane + o < 32) s += v;
            }
            unsigned int higher = s - tot;       // keys in bins of higher lanes
            if (higher < k0 && higher + tot >= k0) {
                unsigned int run = higher;
#pragma unroll
                for (int i = 7; i >= 0; i--) {
                    run += cnt[i];
                    if (run >= k0) {
                        s_prefix = pfx | ((unsigned int)(lane * 8 + i) << shift);
                        s_k = k0 - (run - cnt[i]);
                        break;
                    }
                }
            }
        }
        __syncthreads();
    }

    unsigned int kkey = s_prefix;
    unsigned int bits = (kkey & 0x80000000u) ? (kkey & 0x7FFFFFFFu) : ~kkey;
    float kth = __uint_as_float(bits);

    // masked max (warp-shuffle reduction, 2 barriers)
    float m = -CUDART_INF_F;
    for (int j = tid; j < KV; j += ST)
        if (skey[j] >= kkey) m = fmaxf(m, g_attn[(size_t)bh * KV + j]);
#pragma unroll
    for (int o = 16; o; o >>= 1) m = fmaxf(m, __shfl_xor_sync(FULLMASK, m, o));
    if (lane == 0) sred[warp] = m;
    __syncthreads();
    if (tid < 32) {
        float v = (tid < ST / 32) ? sred[tid] : -CUDART_INF_F;
#pragma unroll
        for (int o = 16; o; o >>= 1) v = fmaxf(v, __shfl_xor_sync(FULLMASK, v, o));
        if (tid == 0) sred[ST / 32] = v;
    }
    __syncthreads();
    m = sred[ST / 32];

    // masked sum of exp
    float z = 0.f;
    for (int j = tid; j < KV; j += ST)
        if (skey[j] >= kkey) z += expf(g_attn[(size_t)bh * KV + j] - m);
#pragma unroll
    for (int o = 16; o; o >>= 1) z += __shfl_xor_sync(FULLMASK, z, o);
    __syncthreads();
    if (lane == 0) sred[warp] = z;
    __syncthreads();
    if (tid == 0) {
        float t = 0.f;
#pragma unroll
        for (int w = 0; w < ST / 32; w++) t += sred[w];
        g_kth[bh] = kth;
        g_m[bh] = m;
        g_invZ[bh] = 1.f / t;
    }
}

// ---------------- K5: selective weighted value accumulation (split 16x) ----
__global__ void outv_kernel(const float* __restrict__ pv) {
    int bh = blockIdx.y;
    int tid = threadIdx.x;
    int warp = tid >> 5, lane = tid & 31;
    float kth = g_kth[bh], m = g_m[bh], invZ = g_invZ[bh];

    float4 acc = make_float4(0.f, 0.f, 0.f, 0.f);
    // 16 blocks x 8 warps = 128 warps stride over KV
    for (int j = blockIdx.x * 8 + warp; j < KV; j += 128) {
        float g = g_gattn[(size_t)bh * KV + j];
        if (g >= kth) {
            float w = expf(g_attn[(size_t)bh * KV + j] - m) * invZ;
            const float* vrow = (j < S_PAST)
                ? pv + ((size_t)bh * S_PAST + j) * HD
                : g_vnew + (size_t)bh * HD;
            float4 v4 = __ldg(&reinterpret_cast<const float4*>(vrow)[lane]);
            acc.x += w * v4.x; acc.y += w * v4.y; acc.z += w * v4.z; acc.w += w * v4.w;
        }
    }
    __shared__ float sacc[8][HD];
    reinterpret_cast<float4*>(&sacc[warp][0])[lane] = acc;
    __syncthreads();
    if (tid < HD) {
        float s = 0.f;
#pragma unroll
        for (int w = 0; w < 8; w++) s += sacc[w][tid];
        atomicAdd(&g_hout[bh * HD + tid], s);
    }
}

// ---------------- K6: output GEMV (hout @ Wo^T) ----------------
__global__ void out_gemv_kernel(const float* __restrict__ Wo,
                                float* __restrict__ out) {
    int row = blockIdx.x;
    const float4* w4 = reinterpret_cast<const float4*>(Wo + (size_t)row * HID);
    const float4* h4 = reinterpret_cast<const float4*>(g_hout);

    float a0 = 0.f, a1 = 0.f, a2 = 0.f, a3 = 0.f;
    for (int i = threadIdx.x; i < HID / 4; i += blockDim.x) {
        float4 w = __ldg(&w4[i]);
        float4 h;
        h = h4[i];
        a0 += w.x * h.x + w.y * h.y + w.z * h.z + w.w * h.w;
        h = h4[i + (HID / 4)];
        a1 += w.x * h.x + w.y * h.y + w.z * h.z + w.w * h.w;
        h = h4[i + 2 * (HID / 4)];
        a2 += w.x * h.x + w.y * h.y + w.z * h.z + w.w * h.w;
        h = h4[i + 3 * (HID / 4)];
        a3 += w.x * h.x + w.y * h.y + w.z * h.z + w.w * h.w;
    }
#pragma unroll
    for (int o = 16; o; o >>= 1) {
        a0 += __shfl_down_sync(FULLMASK, a0, o);
        a1 += __shfl_down_sync(FULLMASK, a1, o);
        a2 += __shfl_down_sync(FULLMASK, a2, o);
        a3 += __shfl_down_sync(FULLMASK, a3, o);
    }
    __shared__ float s[4][4];
    int warp = threadIdx.x >> 5, lane = threadIdx.x & 31;
    if (lane == 0) { s[warp][0] = a0; s[warp][1] = a1; s[warp][2] = a2; s[warp][3] = a3; }
    __syncthreads();
    if (threadIdx.x < 4) {
        float sum = s[0][threadIdx.x] + s[1][threadIdx.x] + s[2][threadIdx.x] + s[3][threadIdx.x];
        out[(size_t)threadIdx.x * HID + row] = sum;
    }
}

// ---------------- launch ----------------
extern "C" void kernel_launch(void* const* d_in, const int* in_sizes, int n_in,
                              void* d_out, int out_size) {
    const float* hid  = (const float*)d_in[0];
    const float* pk   = (const float*)d_in[1];
    const float* pv   = (const float*)d_in[2];
    const float* cosp = (const float*)d_in[3];
    const float* sinp = (const float*)d_in[4];
    const int*   sch  = (const int*)d_in[5];
    const float* Wq   = (const float*)d_in[6];
    const float* Wk   = (const float*)d_in[7];
    const float* Wv   = (const float*)d_in[8];
    const float* Wo   = (const float*)d_in[9];
    float* out = (float*)d_out;

    qkv_gemv_kernel<<<3 * HID, 128>>>(hid, Wq, Wk, Wv);
    rope_kernel<<<BH, 128>>>(cosp, sinp, sch);
    attn_kernel<<<dim3((KV + 31) / 32, BH), 256>>>(pk, sch);
    select_kernel<<<BH, ST>>>();
    outv_kernel<<<dim3(16, BH), 256>>>(pv);
    out_gemv_kernel<<<HID, 128>>>(Wo, out);
}